// round 3
// baseline (speedup 1.0000x reference)
#include <cuda_runtime.h>
#include <cuda_bf16.h>

// Problem: TriggerGenerator_66889820668158
// Inputs (metadata order):
// 0 clean_features f32 [100000,256]
// 1 selected_nodes i32 [10]
// 2 noise          f32 [2038,256]
// 3 gcn1_w f32 [256,64]   4 gcn1_b f32 [64]
// 5 gcn2_w f32 [64,64]    6 gcn2_b f32 [64]
// 7 gcn3_w f32 [64,256]   8 gcn3_b f32 [256]
// 9 ew1    f32 [512,64]  10 eb1    f32 [64]
// 11 ew2   f32 [64,1]    12 eb2    f32 [1]
// Output: concat(trig [2048,256], edge_probs [2096128,1]) = 2620416 f32

#define N_NODES   2048
#define FDIM      256
#define HID       64
#define TEMPLATE  10
#define TRIG_ELEMS (N_NODES * FDIM)

__device__ float g_s[FDIM];
__device__ float g_pa[N_NODES * HID];   // pa + eb1 folded
__device__ float g_pb[N_NODES * HID];

// ---- packed f32x2 helpers (Blackwell FFMA2/FADD2 path) ----------------------
typedef unsigned long long u64;

__device__ __forceinline__ u64 add_f32x2(u64 a, u64 b) {
    u64 r; asm("add.rn.f32x2 %0, %1, %2;" : "=l"(r) : "l"(a), "l"(b)); return r;
}
__device__ __forceinline__ u64 fma_f32x2(u64 a, u64 b, u64 c) {
    u64 r; asm("fma.rn.f32x2 %0, %1, %2, %3;" : "=l"(r) : "l"(a), "l"(b), "l"(c)); return r;
}
__device__ __forceinline__ float lo_f(u64 v) { return __uint_as_float((unsigned)v); }
__device__ __forceinline__ float hi_f(u64 v) { return __uint_as_float((unsigned)(v >> 32)); }
__device__ __forceinline__ u64 pack_f(float lo, float hi) {
    return ((u64)__float_as_uint(hi) << 32) | (u64)__float_as_uint(lo);
}

// ---------------------------------------------------------------------------
// K1: collapse GCN to a single vector chain (all template rows identical,
// A = ones/T maps identical rows to themselves -> one vector through 3 layers).
// ---------------------------------------------------------------------------
__global__ void k1_gcn(const float* __restrict__ clean,
                       const int*   __restrict__ sel,
                       const float* __restrict__ w1, const float* __restrict__ b1,
                       const float* __restrict__ w2, const float* __restrict__ b2,
                       const float* __restrict__ w3, const float* __restrict__ b3)
{
    __shared__ float proto[FDIM];
    __shared__ float h1[HID];
    __shared__ float h2[HID];
    int t = threadIdx.x;  // 256 threads

    float acc = 0.f;
    #pragma unroll
    for (int n = 0; n < TEMPLATE; n++)
        acc += clean[(long long)sel[n] * FDIM + t];
    proto[t] = acc * (1.0f / TEMPLATE);
    __syncthreads();

    if (t < HID) {
        float a = b1[t];
        #pragma unroll 8
        for (int f = 0; f < FDIM; f++) a += proto[f] * w1[f * HID + t];
        h1[t] = fmaxf(a, 0.f);
    }
    __syncthreads();

    if (t < HID) {
        float a = b2[t];
        #pragma unroll 8
        for (int f = 0; f < HID; f++) a += h1[f] * w2[f * HID + t];
        h2[t] = fmaxf(a, 0.f);
    }
    __syncthreads();

    {
        float a = b3[t];
        #pragma unroll 8
        for (int k = 0; k < HID; k++) a += h2[k] * w3[k * FDIM + t];
        g_s[t] = 1.0f / (1.0f + __expf(-a));
    }
}

// ---------------------------------------------------------------------------
// K2: build trig rows (write to out), and pa/pb = trig @ ew1 halves.
// 128 blocks x 256 threads; each block owns 16 rows.
// kk = tid&127 selects output column (kk<64 -> pa, else pb),
// rg = tid>>7 selects which 8 rows. Weights reused across 8 rows in regs.
// ew1 is 128 KB -> L1-resident after first pass.
// ---------------------------------------------------------------------------
__global__ void __launch_bounds__(256)
k2_trig_pab(const float* __restrict__ noise,
            const float* __restrict__ ew1,
            const float* __restrict__ eb1,
            float* __restrict__ out_trig)
{
    __shared__ float s_s[FDIM];
    __shared__ float t_s[16][FDIM];
    int tid = threadIdx.x;            // 256
    s_s[tid] = g_s[tid];
    __syncthreads();

    int base = blockIdx.x * 16;
    #pragma unroll
    for (int r = 0; r < 16; r++) {
        int i = base + r;
        float tv = s_s[tid];
        if (i >= TEMPLATE) tv += 0.1f * noise[(i - TEMPLATE) * FDIM + tid];
        t_s[r][tid] = tv;
        out_trig[i * FDIM + tid] = tv;
    }
    __syncthreads();

    int kk  = tid & 127;
    int rg  = tid >> 7;               // 0/1 -> rows [0..7] / [8..15]
    int col = kk & 63;
    int foff = (kk < HID) ? 0 : FDIM; // pa uses ew1[0:256], pb uses ew1[256:512]

    float acc[8];
    #pragma unroll
    for (int r = 0; r < 8; r++) acc[r] = 0.f;

    #pragma unroll 4
    for (int f = 0; f < FDIM; f += 4) {
        float w0 = ew1[(foff + f    ) * HID + col];
        float w1 = ew1[(foff + f + 1) * HID + col];
        float w2 = ew1[(foff + f + 2) * HID + col];
        float w3 = ew1[(foff + f + 3) * HID + col];
        #pragma unroll
        for (int r = 0; r < 8; r++) {
            float4 t4 = *(const float4*)&t_s[rg * 8 + r][f];
            acc[r] = fmaf(t4.x, w0, acc[r]);
            acc[r] = fmaf(t4.y, w1, acc[r]);
            acc[r] = fmaf(t4.z, w2, acc[r]);
            acc[r] = fmaf(t4.w, w3, acc[r]);
        }
    }

    #pragma unroll
    for (int r = 0; r < 8; r++) {
        int i = base + rg * 8 + r;
        if (kk < HID) g_pa[i * HID + kk]        = acc[r] + eb1[kk];
        else          g_pb[i * HID + (kk - 64)] = acc[r];
    }
}

// ---------------------------------------------------------------------------
// K3: all upper-triangle pairs. 64x64 tiles of (i,j); block returns if tile
// entirely below diagonal. 256 threads, 4x4 register micro-tile, k-dimension
// processed in f32x2 pairs (FADD2 / FFMA2): fma-pipe issue count halved.
// TSTRIDE=66 (even) keeps LDS.64 8-byte aligned; rows m=c+16b give banks
// {2c, 2c+1} -> all 32 banks exactly once -> conflict-free.
// ---------------------------------------------------------------------------
#define TS 64
#define TSTRIDE 66

__global__ void __launch_bounds__(256)
k3_edges(const float* __restrict__ ew2,
         const float* __restrict__ eb2,
         float* __restrict__ out_edge)
{
    int tjb = blockIdx.x;
    int tib = blockIdx.y;
    if (tib > tjb) return;

    __shared__ __align__(8) float pa_s[TS * TSTRIDE];
    __shared__ __align__(8) float pb_s[TS * TSTRIDE];
    __shared__ __align__(8) float w_s[HID];

    int tid = threadIdx.x;  // 256
    int base_i = tib * TS;
    int base_j = tjb * TS;

    for (int idx = tid; idx < TS * HID; idx += 256) {
        int row = idx >> 6, k = idx & 63;
        pa_s[row * TSTRIDE + k] = g_pa[(base_i + row) * HID + k];
        pb_s[row * TSTRIDE + k] = g_pb[(base_j + row) * HID + k];
    }
    if (tid < HID) w_s[tid] = ew2[tid];
    __syncthreads();

    int r = tid >> 4;   // 0..15
    int c = tid & 15;   // 0..15

    u64 acc2[4][4];     // packed (even-k, odd-k) partial sums
    #pragma unroll
    for (int a = 0; a < 4; a++)
        #pragma unroll
        for (int b = 0; b < 4; b++) acc2[a][b] = 0ull;

    #pragma unroll 4
    for (int k = 0; k < HID; k += 2) {
        u64 w2 = *(const u64*)&w_s[k];
        u64 av2[4], bv2[4];
        #pragma unroll
        for (int a = 0; a < 4; a++)
            av2[a] = *(const u64*)&pa_s[(r + 16 * a) * TSTRIDE + k];
        #pragma unroll
        for (int b = 0; b < 4; b++)
            bv2[b] = *(const u64*)&pb_s[(c + 16 * b) * TSTRIDE + k];

        #pragma unroll
        for (int a = 0; a < 4; a++)
            #pragma unroll
            for (int b = 0; b < 4; b++) {
                u64 s = add_f32x2(av2[a], bv2[b]);           // 1 fma-pipe issue
                float h0 = fmaxf(lo_f(s), 0.f);              // alu pipe
                float h1 = fmaxf(hi_f(s), 0.f);              // alu pipe
                acc2[a][b] = fma_f32x2(pack_f(h0, h1), w2, acc2[a][b]); // 1 fma-pipe issue
            }
    }

    float bias = eb2[0];
    #pragma unroll
    for (int a = 0; a < 4; a++) {
        int i = base_i + r + 16 * a;
        // edge index = i*(N-1) - i*(i-1)/2 + (j - i - 1)
        int ebase = i * (N_NODES - 1) - (i * (i - 1)) / 2 - i - 1;
        #pragma unroll
        for (int b = 0; b < 4; b++) {
            int j = base_j + c + 16 * b;
            if (i < j) {
                float x = lo_f(acc2[a][b]) + hi_f(acc2[a][b]) + bias;
                out_edge[ebase + j] = 1.0f / (1.0f + __expf(-x));
            }
        }
    }
}

// ---------------------------------------------------------------------------
extern "C" void kernel_launch(void* const* d_in, const int* in_sizes, int n_in,
                              void* d_out, int out_size)
{
    const float* clean  = (const float*)d_in[0];
    const int*   sel    = (const int*)  d_in[1];
    const float* noise  = (const float*)d_in[2];
    const float* g1w    = (const float*)d_in[3];
    const float* g1b    = (const float*)d_in[4];
    const float* g2w    = (const float*)d_in[5];
    const float* g2b    = (const float*)d_in[6];
    const float* g3w    = (const float*)d_in[7];
    const float* g3b    = (const float*)d_in[8];
    const float* ew1    = (const float*)d_in[9];
    const float* eb1    = (const float*)d_in[10];
    const float* ew2    = (const float*)d_in[11];
    const float* eb2    = (const float*)d_in[12];

    float* out      = (float*)d_out;
    float* out_edge = out + TRIG_ELEMS;

    k1_gcn<<<1, 256>>>(clean, sel, g1w, g1b, g2w, g2b, g3w, g3b);
    k2_trig_pab<<<128, 256>>>(noise, ew1, eb1, out);
    k3_edges<<<dim3(32, 32), 256>>>(ew2, eb2, out_edge);
}